// round 1
// baseline (speedup 1.0000x reference)
#include <cuda_runtime.h>
#include <math.h>

// ---------------- problem constants ----------------
#define M_TOT   65536          // N*L = 16*4096
#define FEAT    512
#define F2      1024           // 2*FEAT
#define NAA     21
#define EMB_OFF 882            // 21*14*3
#define EPSF    1e-6f
#define NT_ROW  533            // max row tiles: 512 + 21 (bucket padding)
#define MP_MAX  (NT_ROW * 128) // 68224 padded rows

// ---------------- scratch (device globals; no allocation allowed) ----------------
__device__ __align__(16) float g_crd[M_TOT * 48];                 // crd14 padded 42->48
__device__ __align__(16) float g_h1[(size_t)MP_MAX * F2];         // 279 MB
__device__ __align__(16) float g_h2[(size_t)MP_MAX * FEAT];       // 140 MB
__device__ __align__(16) float g_h3[(size_t)MP_MAX * FEAT];       // 140 MB
__device__ __align__(16) float g_bias1[NAA * F2];
__device__ int g_counts[NAA];
__device__ int g_fill[NAA];
__device__ int g_offs[NAA];
__device__ int g_perm[MP_MAX];
__device__ int g_tile_aa[NT_ROW];

// ---------------- kernel 0: reset per-launch state ----------------
__global__ void init_kernel() {
    int i = blockIdx.x * blockDim.x + threadIdx.x;
    if (i < MP_MAX) g_perm[i] = -1;
    if (i < NAA) { g_counts[i] = 0; g_fill[i] = 0; }
}

// ---------------- kernel 1: local frames + masked crd + aa histogram ----------------
__global__ void frame_kernel(const int* __restrict__ aa,
                             const float* __restrict__ pos14,
                             const int* __restrict__ mask) {
    int m = blockIdx.x * blockDim.x + threadIdx.x;
    if (m >= M_TOT) return;
    int a = aa[m];
    atomicAdd(&g_counts[a], 1);

    const float* p = pos14 + (size_t)m * 42;
    float cx = p[3], cy = p[4], cz = p[5];                 // atom 1 = center
    float v1x = p[6] - cx, v1y = p[7] - cy, v1z = p[8] - cz;  // atom2 - center
    float n1 = sqrtf(v1x*v1x + v1y*v1y + v1z*v1z) + EPSF;
    float e1x = v1x / n1, e1y = v1y / n1, e1z = v1z / n1;
    float v2x = p[0] - cx, v2y = p[1] - cy, v2z = p[2] - cz;  // atom0 - center
    float d  = e1x*v2x + e1y*v2y + e1z*v2z;
    float u2x = v2x - d*e1x, u2y = v2y - d*e1y, u2z = v2z - d*e1z;
    float n2 = sqrtf(u2x*u2x + u2y*u2y + u2z*u2z) + EPSF;
    float e2x = u2x / n2, e2y = u2y / n2, e2z = u2z / n2;
    float e3x = e1y*e2z - e1z*e2y;
    float e3y = e1z*e2x - e1x*e2z;
    float e3z = e1x*e2y - e1y*e2x;

    float* out = g_crd + (size_t)m * 48;
#pragma unroll
    for (int at = 0; at < 14; at++) {
        float qx = p[at*3+0] - cx, qy = p[at*3+1] - cy, qz = p[at*3+2] - cz;
        bool mk = mask[m*14 + at] != 0;
        out[at*3+0] = mk ? (e1x*qx + e1y*qy + e1z*qz) : 0.f;
        out[at*3+1] = mk ? (e2x*qx + e2y*qy + e2z*qz) : 0.f;
        out[at*3+2] = mk ? (e3x*qx + e3y*qy + e3z*qz) : 0.f;
    }
#pragma unroll
    for (int k = 42; k < 48; k++) out[k] = 0.f;
}

// ---------------- kernel 2: bucket plan (padded offsets + tile->aa map) ----------------
__global__ void plan_kernel() {
    int off = 0, t = 0;
    for (int a = 0; a < NAA; a++) {
        g_offs[a] = off;
        int nt = (g_counts[a] + 127) >> 7;
        for (int i = 0; i < nt; i++) g_tile_aa[t++] = a;
        off += nt << 7;
    }
    for (; t < NT_ROW; t++) g_tile_aa[t] = -1;
}

// ---------------- kernel 3: scatter rows into buckets ----------------
__global__ void scatter_kernel(const int* __restrict__ aa) {
    int m = blockIdx.x * blockDim.x + threadIdx.x;
    if (m >= M_TOT) return;
    int a = aa[m];
    int pos = atomicAdd(&g_fill[a], 1);
    g_perm[g_offs[a] + pos] = m;
}

// ---------------- kernel 4: bias1_aa = b1 + embed[a] @ w1[882:] ----------------
__global__ void bias1_kernel(const float* __restrict__ embed,
                             const float* __restrict__ w1,
                             const float* __restrict__ b1) {
    int a = blockIdx.y;
    int j = blockIdx.x * 128 + threadIdx.x;
    float acc = b1[j];
    for (int k = 0; k < FEAT; k++)
        acc += embed[a * FEAT + k] * w1[(size_t)(EMB_OFF + k) * F2 + j];
    g_bias1[a * F2 + j] = acc;
}

// ---------------- kernel 5: GEMM1 (gathered rows, per-class weight block, K=48) ----------------
__global__ __launch_bounds__(256) void gemm1_kernel(const float* __restrict__ w1) {
    __shared__ float As[48][128];
    __shared__ float Bs[48][128];
    int bx = blockIdx.x;             // col tile (8 over 1024)
    int by = blockIdx.y;             // row tile
    int cls = g_tile_aa[by];
    if (cls < 0) return;
    int tid = threadIdx.x;
    int c0 = bx * 128;
    int rowbase = by * 128;

    // weights: 48x128 (rows >= 42 are zero)
#pragma unroll
    for (int i = 0; i < 6; i++) {
        int lin = tid + i * 256;           // float4 index, 0..1535
        int k = lin >> 5, cq = (lin & 31) * 4;
        float4 v = make_float4(0.f, 0.f, 0.f, 0.f);
        if (k < 42) v = *(const float4*)(w1 + (size_t)(cls * 42 + k) * F2 + c0 + cq);
        *(float4*)&Bs[k][cq] = v;
    }
    // gathered A rows
    int row = tid >> 1, part = tid & 1;
    int m = g_perm[rowbase + row];
#pragma unroll
    for (int i = 0; i < 6; i++) {
        float4 v = make_float4(0.f, 0.f, 0.f, 0.f);
        if (m >= 0) v = *(const float4*)(g_crd + (size_t)m * 48 + part * 24 + i * 4);
        int k = part * 24 + i * 4;
        As[k][row] = v.x; As[k+1][row] = v.y; As[k+2][row] = v.z; As[k+3][row] = v.w;
    }
    __syncthreads();

    int tx = tid & 15, ty = tid >> 4;
    int ra = ty * 4, rb = ra + 64, ca = tx * 4, cb = ca + 64;
    float acc[8][8] = {};
#pragma unroll
    for (int k = 0; k < 48; k++) {
        float af[8], bf[8];
        *(float4*)(af)     = *(float4*)&As[k][ra];
        *(float4*)(af + 4) = *(float4*)&As[k][rb];
        *(float4*)(bf)     = *(float4*)&Bs[k][ca];
        *(float4*)(bf + 4) = *(float4*)&Bs[k][cb];
#pragma unroll
        for (int i = 0; i < 8; i++)
#pragma unroll
            for (int j = 0; j < 8; j++) acc[i][j] += af[i] * bf[j];
    }

    const float* bp = g_bias1 + cls * F2 + c0;
#pragma unroll
    for (int i = 0; i < 8; i++) {
        int r = rowbase + ((i < 4) ? (ra + i) : (rb + i - 4));
        float* dst = g_h1 + (size_t)r * F2 + c0;
        float4 v;
        v.x = fmaxf(acc[i][0] + bp[ca+0], 0.f);
        v.y = fmaxf(acc[i][1] + bp[ca+1], 0.f);
        v.z = fmaxf(acc[i][2] + bp[ca+2], 0.f);
        v.w = fmaxf(acc[i][3] + bp[ca+3], 0.f);
        *(float4*)(dst + ca) = v;
        v.x = fmaxf(acc[i][4] + bp[cb+0], 0.f);
        v.y = fmaxf(acc[i][5] + bp[cb+1], 0.f);
        v.z = fmaxf(acc[i][6] + bp[cb+2], 0.f);
        v.w = fmaxf(acc[i][7] + bp[cb+3], 0.f);
        *(float4*)(dst + cb) = v;
    }
}

// ---------------- generic tiled SGEMM: C = [relu](A @ W + bias), optional scatter-out ----------------
template<int K, int NC, bool RELU, bool SCATTER>
__global__ __launch_bounds__(256) void gemm_kernel(const float* __restrict__ A,
                                                   const float* __restrict__ W,
                                                   const float* __restrict__ bias,
                                                   float* __restrict__ C) {
    __shared__ float As[8][132];   // padded: conflict-free transposed stores, 16B-aligned rows
    __shared__ float Bs[8][128];
    int bx = blockIdx.x, by = blockIdx.y, tid = threadIdx.x;
    int c0 = bx * 128, rowbase = by * 128;

    int lrow = tid >> 1, lpart = tid & 1;
    const float* Ap = A + (size_t)(rowbase + lrow) * K + lpart * 4;
    int bk = tid >> 5, bc = (tid & 31) * 4;
    const float* Wp = W + (size_t)bk * NC + c0 + bc;

    int tx = tid & 15, ty = tid >> 4;
    int ra = ty * 4, rb = ra + 64, ca = tx * 4, cb = ca + 64;
    float acc[8][8] = {};

    for (int k0 = 0; k0 < K; k0 += 8) {
        float4 av = *(const float4*)(Ap + k0);
        float4 bv = *(const float4*)(Wp + (size_t)k0 * NC);
        __syncthreads();
        int kk = lpart * 4;
        As[kk+0][lrow] = av.x; As[kk+1][lrow] = av.y;
        As[kk+2][lrow] = av.z; As[kk+3][lrow] = av.w;
        *(float4*)&Bs[bk][bc] = bv;
        __syncthreads();
#pragma unroll
        for (int k = 0; k < 8; k++) {
            float af[8], bf[8];
            *(float4*)(af)     = *(float4*)&As[k][ra];
            *(float4*)(af + 4) = *(float4*)&As[k][rb];
            *(float4*)(bf)     = *(float4*)&Bs[k][ca];
            *(float4*)(bf + 4) = *(float4*)&Bs[k][cb];
#pragma unroll
            for (int i = 0; i < 8; i++)
#pragma unroll
                for (int j = 0; j < 8; j++) acc[i][j] += af[i] * bf[j];
        }
    }

#pragma unroll
    for (int i = 0; i < 8; i++) {
        int r = rowbase + ((i < 4) ? (ra + i) : (rb + i - 4));
        float* dst;
        if (SCATTER) {
            int m = g_perm[r];
            if (m < 0) continue;
            dst = C + (size_t)m * NC + c0;
        } else {
            dst = C + (size_t)r * NC + c0;
        }
        float4 v;
        v.x = acc[i][0] + bias[c0+ca+0];
        v.y = acc[i][1] + bias[c0+ca+1];
        v.z = acc[i][2] + bias[c0+ca+2];
        v.w = acc[i][3] + bias[c0+ca+3];
        if (RELU) { v.x=fmaxf(v.x,0.f); v.y=fmaxf(v.y,0.f); v.z=fmaxf(v.z,0.f); v.w=fmaxf(v.w,0.f); }
        *(float4*)(dst + ca) = v;
        v.x = acc[i][4] + bias[c0+cb+0];
        v.y = acc[i][5] + bias[c0+cb+1];
        v.z = acc[i][6] + bias[c0+cb+2];
        v.w = acc[i][7] + bias[c0+cb+3];
        if (RELU) { v.x=fmaxf(v.x,0.f); v.y=fmaxf(v.y,0.f); v.z=fmaxf(v.z,0.f); v.w=fmaxf(v.w,0.f); }
        *(float4*)(dst + cb) = v;
    }
}

// ---------------- launch ----------------
extern "C" void kernel_launch(void* const* d_in, const int* in_sizes, int n_in,
                              void* d_out, int out_size) {
    const int*   aa    = (const int*)  d_in[0];
    const float* pos14 = (const float*)d_in[1];
    const int*   mask  = (const int*)  d_in[2];
    const float* embed = (const float*)d_in[3];
    const float* w1    = (const float*)d_in[4];
    const float* b1    = (const float*)d_in[5];
    const float* w2    = (const float*)d_in[6];
    const float* b2    = (const float*)d_in[7];
    const float* w3    = (const float*)d_in[8];
    const float* b3    = (const float*)d_in[9];
    const float* w4    = (const float*)d_in[10];
    const float* b4    = (const float*)d_in[11];
    float* out = (float*)d_out;

    void *p_h1, *p_h2, *p_h3;
    cudaGetSymbolAddress(&p_h1, g_h1);
    cudaGetSymbolAddress(&p_h2, g_h2);
    cudaGetSymbolAddress(&p_h3, g_h3);

    init_kernel<<<(MP_MAX + 255) / 256, 256>>>();
    frame_kernel<<<M_TOT / 256, 256>>>(aa, pos14, mask);
    plan_kernel<<<1, 1>>>();
    scatter_kernel<<<M_TOT / 256, 256>>>(aa);
    bias1_kernel<<<dim3(F2 / 128, NAA), 128>>>(embed, w1, b1);

    gemm1_kernel<<<dim3(F2 / 128, NT_ROW), 256>>>(w1);
    gemm_kernel<F2, FEAT, true,  false><<<dim3(FEAT / 128, NT_ROW), 256>>>((const float*)p_h1, w2, b2, (float*)p_h2);
    gemm_kernel<FEAT, FEAT, true,  false><<<dim3(FEAT / 128, NT_ROW), 256>>>((const float*)p_h2, w3, b3, (float*)p_h3);
    gemm_kernel<FEAT, FEAT, false, true ><<<dim3(FEAT / 128, NT_ROW), 256>>>((const float*)p_h3, w4, b4, out);
    (void)in_sizes; (void)n_in; (void)out_size;
}

// round 3
// speedup vs baseline: 2.8524x; 2.8524x over previous
#include <cuda_runtime.h>
#include <cstdint>
#include <math.h>

// ---------------- problem constants ----------------
#define M_TOT   65536
#define FEAT    512
#define F2      1024
#define NAA     21
#define EPSF    1e-6f
#define NT_ROW  533
#define MP_MAX  (NT_ROW * 128)

// ---------------- device scratch ----------------
__device__ __align__(16) float g_crd[M_TOT * 48];
__device__ __align__(16) float g_h1[(size_t)MP_MAX * F2];
__device__ __align__(16) float g_h2[(size_t)MP_MAX * FEAT];
__device__ __align__(16) float g_h3[(size_t)MP_MAX * FEAT];
__device__ __align__(16) float g_w1p[NAA * 48 * F2];     // [cls][k<48][n], tf32, zero pad k>=42
__device__ __align__(16) float g_w2r[F2 * FEAT];         // [k][n] tf32-rounded
__device__ __align__(16) float g_w3r[FEAT * FEAT];
__device__ __align__(16) float g_w4r[FEAT * FEAT];
__device__ __align__(16) float g_bias1[NAA * F2];
__device__ int g_counts[NAA];
__device__ int g_fill[NAA];
__device__ int g_offs[NAA];
__device__ int g_perm[MP_MAX];
__device__ int g_tile_aa[NT_ROW];

// ---------------- helpers ----------------
__device__ __forceinline__ uint32_t smem_u32(const void* p) {
    uint32_t a;
    asm("{ .reg .u64 t; cvta.to.shared.u64 t, %1; cvt.u32.u64 %0, t; }" : "=r"(a) : "l"(p));
    return a;
}
__device__ __forceinline__ float to_tf32(float x) {
    float r; asm("cvt.rna.tf32.f32 %0, %1;" : "=f"(r) : "f"(x)); return r;
}
__device__ __forceinline__ void cp16(uint32_t dst, const void* src) {
    asm volatile("cp.async.cg.shared.global [%0], [%1], 16;" :: "r"(dst), "l"(src));
}
#define CP_COMMIT() asm volatile("cp.async.commit_group;" ::: "memory")
#define CP_WAIT(n)  asm volatile("cp.async.wait_group %0;" :: "n"(n) : "memory")

__device__ __forceinline__ void mma8(float* c, const uint32_t* a, const uint32_t* b) {
    asm volatile(
        "mma.sync.aligned.m16n8k8.row.col.f32.tf32.tf32.f32 "
        "{%0,%1,%2,%3}, {%4,%5,%6,%7}, {%8,%9}, {%0,%1,%2,%3};"
        : "+f"(c[0]), "+f"(c[1]), "+f"(c[2]), "+f"(c[3])
        : "r"(a[0]), "r"(a[1]), "r"(a[2]), "r"(a[3]), "r"(b[0]), "r"(b[1]));
}

// smem strides (floats) chosen conflict-free for fragment loads
#define SA 20     // A: addr = m*20 + k   -> 32 distinct banks over (gid,tig)
#define SB 136    // B: addr = k*136 + n  -> 32 distinct banks over (tig,gid)

// ---------------- preprocessing ----------------
__global__ void init_kernel() {
    int i = blockIdx.x * blockDim.x + threadIdx.x;
    if (i < MP_MAX) g_perm[i] = -1;
    if (i < NAA) { g_counts[i] = 0; g_fill[i] = 0; }
}

__global__ void frame_kernel(const int* __restrict__ aa,
                             const float* __restrict__ pos14,
                             const int* __restrict__ mask) {
    int m = blockIdx.x * blockDim.x + threadIdx.x;
    if (m >= M_TOT) return;
    int a = aa[m];
    atomicAdd(&g_counts[a], 1);

    const float* p = pos14 + (size_t)m * 42;
    float cx = p[3], cy = p[4], cz = p[5];
    float v1x = p[6] - cx, v1y = p[7] - cy, v1z = p[8] - cz;
    float n1 = sqrtf(v1x*v1x + v1y*v1y + v1z*v1z) + EPSF;
    float e1x = v1x / n1, e1y = v1y / n1, e1z = v1z / n1;
    float v2x = p[0] - cx, v2y = p[1] - cy, v2z = p[2] - cz;
    float d  = e1x*v2x + e1y*v2y + e1z*v2z;
    float u2x = v2x - d*e1x, u2y = v2y - d*e1y, u2z = v2z - d*e1z;
    float n2 = sqrtf(u2x*u2x + u2y*u2y + u2z*u2z) + EPSF;
    float e2x = u2x / n2, e2y = u2y / n2, e2z = u2z / n2;
    float e3x = e1y*e2z - e1z*e2y;
    float e3y = e1z*e2x - e1x*e2z;
    float e3z = e1x*e2y - e1y*e2x;

    float* out = g_crd + (size_t)m * 48;
#pragma unroll
    for (int at = 0; at < 14; at++) {
        float qx = p[at*3+0] - cx, qy = p[at*3+1] - cy, qz = p[at*3+2] - cz;
        bool mk = mask[m*14 + at] != 0;
        out[at*3+0] = mk ? to_tf32(e1x*qx + e1y*qy + e1z*qz) : 0.f;
        out[at*3+1] = mk ? to_tf32(e2x*qx + e2y*qy + e2z*qz) : 0.f;
        out[at*3+2] = mk ? to_tf32(e3x*qx + e3y*qy + e3z*qz) : 0.f;
    }
#pragma unroll
    for (int k = 42; k < 48; k++) out[k] = 0.f;
}

__global__ void plan_kernel() {
    int off = 0, t = 0;
    for (int a = 0; a < NAA; a++) {
        g_offs[a] = off;
        int nt = (g_counts[a] + 127) >> 7;
        for (int i = 0; i < nt; i++) g_tile_aa[t++] = a;
        off += nt << 7;
    }
    for (; t < NT_ROW; t++) g_tile_aa[t] = -1;
}

__global__ void scatter_kernel(const int* __restrict__ aa) {
    int m = blockIdx.x * blockDim.x + threadIdx.x;
    if (m >= M_TOT) return;
    int a = aa[m];
    int pos = atomicAdd(&g_fill[a], 1);
    g_perm[g_offs[a] + pos] = m;
}

__global__ void bias1_kernel(const float* __restrict__ embed,
                             const float* __restrict__ w1,
                             const float* __restrict__ b1) {
    int a = blockIdx.y;
    int j = blockIdx.x * 128 + threadIdx.x;
    float acc = b1[j];
    for (int k = 0; k < FEAT; k++)
        acc += embed[a * FEAT + k] * w1[(size_t)(882 + k) * F2 + j];
    g_bias1[a * F2 + j] = acc;
}

// g_w1p[cls][k][n] = tf32(w1[cls*42+k][n]), 0 for k in [42,48)
__global__ void w1p_kernel(const float* __restrict__ w1) {
    int i = blockIdx.x * blockDim.x + threadIdx.x;
    if (i >= NAA * 48 * F2) return;
    int n = i & (F2 - 1);
    int r = i >> 10;
    int k = r % 48, cls = r / 48;
    float v = (k < 42) ? to_tf32(w1[(size_t)(cls * 42 + k) * F2 + n]) : 0.f;
    g_w1p[i] = v;
}

__global__ void round_kernel(const float* __restrict__ src, float* __restrict__ dst, int n) {
    int i = blockIdx.x * blockDim.x + threadIdx.x;
    if (i < n) dst[i] = to_tf32(src[i]);
}

// ---------------- mma.sync GEMM, layers 2-4 (N = 512) ----------------
// CTA: 128 rows x 128 cols; 8 warps (2 m x 4 n), warp tile 64x32.
template<int K, bool RELU, bool SCATTER>
__global__ __launch_bounds__(256, 2) void gemm_mma(const float* __restrict__ A,
                                                   const float* __restrict__ W,
                                                   const float* __restrict__ bias,
                                                   float* __restrict__ C) {
    int by = blockIdx.y;
    if (g_tile_aa[by] < 0) return;
    __shared__ float As[2][128][SA];
    __shared__ float Bs[2][16][SB];

    int tid = threadIdx.x;
    int bx = blockIdx.x;
    int rowbase = by * 128;
    int c_base = bx * 128;

    int wid = tid >> 5, lane = tid & 31;
    int wm = wid & 1, wn = wid >> 1;
    int gid = lane >> 2, tig = lane & 3;

    // cp.async addressing (2 chunks each for A and B per tile)
    int fa0 = tid, fa1 = tid + 256;
    int ar0 = fa0 >> 2, asg0 = fa0 & 3;
    int ar1 = fa1 >> 2, asg1 = fa1 & 3;
    int br0 = fa0 >> 5, bsg0 = fa0 & 31;
    int br1 = fa1 >> 5, bsg1 = fa1 & 31;
    const float* Ab = A + (size_t)rowbase * K;

    const int NS = K / 16;
    float acc[4][4][4];
#pragma unroll
    for (int i = 0; i < 4; i++)
#pragma unroll
        for (int j = 0; j < 4; j++)
#pragma unroll
            for (int q = 0; q < 4; q++) acc[i][j][q] = 0.f;

    // prologue: load tile 0
    {
        cp16(smem_u32(&As[0][ar0][asg0 * 4]), Ab + (size_t)ar0 * K + asg0 * 4);
        cp16(smem_u32(&As[0][ar1][asg1 * 4]), Ab + (size_t)ar1 * K + asg1 * 4);
        cp16(smem_u32(&Bs[0][br0][bsg0 * 4]), W + (size_t)br0 * 512 + c_base + bsg0 * 4);
        cp16(smem_u32(&Bs[0][br1][bsg1 * 4]), W + (size_t)br1 * 512 + c_base + bsg1 * 4);
        CP_COMMIT();
    }

    for (int s = 0; s < NS; s++) {
        int b = s & 1;
        if (s + 1 < NS) {
            int nb = b ^ 1, ko = (s + 1) * 16;
            cp16(smem_u32(&As[nb][ar0][asg0 * 4]), Ab + (size_t)ar0 * K + ko + asg0 * 4);
            cp16(smem_u32(&As[nb][ar1][asg1 * 4]), Ab + (size_t)ar1 * K + ko + asg1 * 4);
            cp16(smem_u32(&Bs[nb][br0][bsg0 * 4]), W + (size_t)(ko + br0) * 512 + c_base + bsg0 * 4);
            cp16(smem_u32(&Bs[nb][br1][bsg1 * 4]), W + (size_t)(ko + br1) * 512 + c_base + bsg1 * 4);
            CP_COMMIT();
            CP_WAIT(1);
        } else {
            CP_WAIT(0);
        }
        __syncthreads();
#pragma unroll
        for (int kt = 0; kt < 2; kt++) {
            int kb = kt * 8;
            uint32_t af[4][4], bf[4][2];
#pragma unroll
            for (int mt = 0; mt < 4; mt++) {
                int am = wm * 64 + mt * 16 + gid;
                af[mt][0] = __float_as_uint(As[b][am][kb + tig]);
                af[mt][1] = __float_as_uint(As[b][am + 8][kb + tig]);
                af[mt][2] = __float_as_uint(As[b][am][kb + tig + 4]);
                af[mt][3] = __float_as_uint(As[b][am + 8][kb + tig + 4]);
            }
#pragma unroll
            for (int nt = 0; nt < 4; nt++) {
                int bn = wn * 32 + nt * 8 + gid;
                bf[nt][0] = __float_as_uint(Bs[b][kb + tig][bn]);
                bf[nt][1] = __float_as_uint(Bs[b][kb + tig + 4][bn]);
            }
#pragma unroll
            for (int mt = 0; mt < 4; mt++)
#pragma unroll
                for (int nt = 0; nt < 4; nt++)
                    mma8(acc[mt][nt], af[mt], bf[nt]);
        }
        __syncthreads();
    }

    // epilogue
#pragma unroll
    for (int mt = 0; mt < 4; mt++) {
        int r0 = rowbase + wm * 64 + mt * 16 + gid;
        int r1 = r0 + 8;
        float *d0 = nullptr, *d1 = nullptr;
        if (SCATTER) {
            int m0 = g_perm[r0], m1 = g_perm[r1];
            if (m0 >= 0) d0 = C + (size_t)m0 * FEAT;
            if (m1 >= 0) d1 = C + (size_t)m1 * FEAT;
        } else {
            d0 = C + (size_t)r0 * FEAT;
            d1 = C + (size_t)r1 * FEAT;
        }
#pragma unroll
        for (int nt = 0; nt < 4; nt++) {
            int c = c_base + wn * 32 + nt * 8 + tig * 2;
            float bx0 = bias[c], bx1 = bias[c + 1];
            float2 v0, v1;
            v0.x = acc[mt][nt][0] + bx0; v0.y = acc[mt][nt][1] + bx1;
            v1.x = acc[mt][nt][2] + bx0; v1.y = acc[mt][nt][3] + bx1;
            if (RELU) {
                v0.x = to_tf32(fmaxf(v0.x, 0.f)); v0.y = to_tf32(fmaxf(v0.y, 0.f));
                v1.x = to_tf32(fmaxf(v1.x, 0.f)); v1.y = to_tf32(fmaxf(v1.y, 0.f));
            }
            if (d0) *(float2*)(d0 + c) = v0;
            if (d1) *(float2*)(d1 + c) = v1;
        }
    }
}

// ---------------- mma.sync GEMM, layer 1 (gathered A, per-class W, K=48, N=1024) ----------------
__global__ __launch_bounds__(256, 2) void gemm1_mma() {
    int by = blockIdx.y;
    int cls = g_tile_aa[by];
    if (cls < 0) return;
    __shared__ float As[2][128][SA];
    __shared__ float Bs[2][16][SB];

    int tid = threadIdx.x;
    int bx = blockIdx.x;               // 0..7 over N=1024
    int rowbase = by * 128;
    int c_base = bx * 128;

    int wid = tid >> 5, lane = tid & 31;
    int wm = wid & 1, wn = wid >> 1;
    int gid = lane >> 2, tig = lane & 3;

    int fa0 = tid, fa1 = tid + 256;
    int ar0 = fa0 >> 2, asg0 = fa0 & 3;
    int ar1 = fa1 >> 2, asg1 = fa1 & 3;
    int br0 = fa0 >> 5, bsg0 = fa0 & 31;
    int br1 = fa1 >> 5, bsg1 = fa1 & 31;

    int m0g = g_perm[rowbase + ar0]; if (m0g < 0) m0g = 0;
    int m1g = g_perm[rowbase + ar1]; if (m1g < 0) m1g = 0;
    const float* Wb = g_w1p + (size_t)cls * 48 * F2;

    const int NS = 3;
    float acc[4][4][4];
#pragma unroll
    for (int i = 0; i < 4; i++)
#pragma unroll
        for (int j = 0; j < 4; j++)
#pragma unroll
            for (int q = 0; q < 4; q++) acc[i][j][q] = 0.f;

    {
        cp16(smem_u32(&As[0][ar0][asg0 * 4]), g_crd + (size_t)m0g * 48 + asg0 * 4);
        cp16(smem_u32(&As[0][ar1][asg1 * 4]), g_crd + (size_t)m1g * 48 + asg1 * 4);
        cp16(smem_u32(&Bs[0][br0][bsg0 * 4]), Wb + (size_t)br0 * F2 + c_base + bsg0 * 4);
        cp16(smem_u32(&Bs[0][br1][bsg1 * 4]), Wb + (size_t)br1 * F2 + c_base + bsg1 * 4);
        CP_COMMIT();
    }

    for (int s = 0; s < NS; s++) {
        int b = s & 1;
        if (s + 1 < NS) {
            int nb = b ^ 1, ko = (s + 1) * 16;
            cp16(smem_u32(&As[nb][ar0][asg0 * 4]), g_crd + (size_t)m0g * 48 + ko + asg0 * 4);
            cp16(smem_u32(&As[nb][ar1][asg1 * 4]), g_crd + (size_t)m1g * 48 + ko + asg1 * 4);
            cp16(smem_u32(&Bs[nb][br0][bsg0 * 4]), Wb + (size_t)(ko + br0) * F2 + c_base + bsg0 * 4);
            cp16(smem_u32(&Bs[nb][br1][bsg1 * 4]), Wb + (size_t)(ko + br1) * F2 + c_base + bsg1 * 4);
            CP_COMMIT();
            CP_WAIT(1);
        } else {
            CP_WAIT(0);
        }
        __syncthreads();
#pragma unroll
        for (int kt = 0; kt < 2; kt++) {
            int kb = kt * 8;
            uint32_t af[4][4], bf[4][2];
#pragma unroll
            for (int mt = 0; mt < 4; mt++) {
                int am = wm * 64 + mt * 16 + gid;
                af[mt][0] = __float_as_uint(As[b][am][kb + tig]);
                af[mt][1] = __float_as_uint(As[b][am + 8][kb + tig]);
                af[mt][2] = __float_as_uint(As[b][am][kb + tig + 4]);
                af[mt][3] = __float_as_uint(As[b][am + 8][kb + tig + 4]);
            }
#pragma unroll
            for (int nt = 0; nt < 4; nt++) {
                int bn = wn * 32 + nt * 8 + gid;
                bf[nt][0] = __float_as_uint(Bs[b][kb + tig][bn]);
                bf[nt][1] = __float_as_uint(Bs[b][kb + tig + 4][bn]);
            }
#pragma unroll
            for (int mt = 0; mt < 4; mt++)
#pragma unroll
                for (int nt = 0; nt < 4; nt++)
                    mma8(acc[mt][nt], af[mt], bf[nt]);
        }
        __syncthreads();
    }

    const float* bp = g_bias1 + cls * F2;
#pragma unroll
    for (int mt = 0; mt < 4; mt++) {
        int r0 = rowbase + wm * 64 + mt * 16 + gid;
        float* d0 = g_h1 + (size_t)r0 * F2;
        float* d1 = d0 + (size_t)8 * F2;
#pragma unroll
        for (int nt = 0; nt < 4; nt++) {
            int c = c_base + wn * 32 + nt * 8 + tig * 2;
            float bx0 = bp[c], bx1 = bp[c + 1];
            float2 v0, v1;
            v0.x = to_tf32(fmaxf(acc[mt][nt][0] + bx0, 0.f));
            v0.y = to_tf32(fmaxf(acc[mt][nt][1] + bx1, 0.f));
            v1.x = to_tf32(fmaxf(acc[mt][nt][2] + bx0, 0.f));
            v1.y = to_tf32(fmaxf(acc[mt][nt][3] + bx1, 0.f));
            *(float2*)(d0 + c) = v0;
            *(float2*)(d1 + c) = v1;
        }
    }
}

// ---------------- launch ----------------
extern "C" void kernel_launch(void* const* d_in, const int* in_sizes, int n_in,
                              void* d_out, int out_size) {
    const int*   aa    = (const int*)  d_in[0];
    const float* pos14 = (const float*)d_in[1];
    const int*   mask  = (const int*)  d_in[2];
    const float* embed = (const float*)d_in[3];
    const float* w1    = (const float*)d_in[4];
    const float* b1    = (const float*)d_in[5];
    const float* w2    = (const float*)d_in[6];
    const float* b2    = (const float*)d_in[7];
    const float* w3    = (const float*)d_in[8];
    const float* b3    = (const float*)d_in[9];
    const float* w4    = (const float*)d_in[10];
    const float* b4    = (const float*)d_in[11];
    float* out = (float*)d_out;

    void *p_h1, *p_h2, *p_h3, *p_w2r, *p_w3r, *p_w4r;
    cudaGetSymbolAddress(&p_h1, g_h1);
    cudaGetSymbolAddress(&p_h2, g_h2);
    cudaGetSymbolAddress(&p_h3, g_h3);
    cudaGetSymbolAddress(&p_w2r, g_w2r);
    cudaGetSymbolAddress(&p_w3r, g_w3r);
    cudaGetSymbolAddress(&p_w4r, g_w4r);

    init_kernel<<<(MP_MAX + 255) / 256, 256>>>();
    frame_kernel<<<M_TOT / 256, 256>>>(aa, pos14, mask);
    plan_kernel<<<1, 1>>>();
    scatter_kernel<<<M_TOT / 256, 256>>>(aa);
    bias1_kernel<<<dim3(F2 / 128, NAA), 128>>>(embed, w1, b1);
    w1p_kernel<<<(NAA * 48 * F2 + 255) / 256, 256>>>(w1);
    round_kernel<<<(F2 * FEAT + 255) / 256, 256>>>(w2, (float*)p_w2r, F2 * FEAT);
    round_kernel<<<(FEAT * FEAT + 255) / 256, 256>>>(w3, (float*)p_w3r, FEAT * FEAT);
    round_kernel<<<(FEAT * FEAT + 255) / 256, 256>>>(w4, (float*)p_w4r, FEAT * FEAT);

    gemm1_mma<<<dim3(8, NT_ROW), 256>>>();
    gemm_mma<1024, true,  false><<<dim3(4, NT_ROW), 256>>>((const float*)p_h1, (const float*)p_w2r, b2, (float*)p_h2);
    gemm_mma<512,  true,  false><<<dim3(4, NT_ROW), 256>>>((const float*)p_h2, (const float*)p_w3r, b3, (float*)p_h3);
    gemm_mma<512,  false, true ><<<dim3(4, NT_ROW), 256>>>((const float*)p_h3, (const float*)p_w4r, b4, out);
    (void)in_sizes; (void)n_in; (void)out_size;
}

// round 5
// speedup vs baseline: 2.9761x; 1.0434x over previous
#include <cuda_runtime.h>
#include <cstdint>
#include <math.h>

// ---------------- problem constants ----------------
#define M_TOT   65536
#define FEAT    512
#define F2      1024
#define NAA     21
#define EPSF    1e-6f
#define NT_ROW  533
#define MP_MAX  (NT_ROW * 128)

// ---------------- device scratch ----------------
__device__ __align__(16) float g_crd[M_TOT * 48];
__device__ __align__(16) float g_h1[(size_t)MP_MAX * F2];
__device__ __align__(16) float g_h2[(size_t)MP_MAX * FEAT];
__device__ __align__(16) float g_h3[(size_t)MP_MAX * FEAT];
__device__ __align__(16) float g_w1p[NAA * 48 * F2];
__device__ __align__(16) float g_w2r[F2 * FEAT];
__device__ __align__(16) float g_w3r[FEAT * FEAT];
__device__ __align__(16) float g_w4r[FEAT * FEAT];
__device__ __align__(16) float g_bias1[NAA * F2];
__device__ int g_counts[NAA];
__device__ int g_fill[NAA];
__device__ int g_offs[NAA];
__device__ int g_perm[MP_MAX];
__device__ int g_tile_aa[NT_ROW];

// ---------------- helpers ----------------
__device__ __forceinline__ uint32_t smem_u32(const void* p) {
    uint32_t a;
    asm("{ .reg .u64 t; cvta.to.shared.u64 t, %1; cvt.u32.u64 %0, t; }" : "=r"(a) : "l"(p));
    return a;
}
__device__ __forceinline__ float to_tf32(float x) {
    float r; asm("cvt.rna.tf32.f32 %0, %1;" : "=f"(r) : "f"(x)); return r;
}
__device__ __forceinline__ void cp16(uint32_t dst, const void* src) {
    asm volatile("cp.async.cg.shared.global [%0], [%1], 16;" :: "r"(dst), "l"(src));
}
#define CP_COMMIT() asm volatile("cp.async.commit_group;" ::: "memory")
#define CP_WAIT(n)  asm volatile("cp.async.wait_group %0;" :: "n"(n) : "memory")

__device__ __forceinline__ void mma8(float* c, const uint32_t* a, const uint32_t* b) {
    asm volatile(
        "mma.sync.aligned.m16n8k8.row.col.f32.tf32.tf32.f32 "
        "{%0,%1,%2,%3}, {%4,%5,%6,%7}, {%8,%9}, {%0,%1,%2,%3};"
        : "+f"(c[0]), "+f"(c[1]), "+f"(c[2]), "+f"(c[3])
        : "r"(a[0]), "r"(a[1]), "r"(a[2]), "r"(a[3]), "r"(b[0]), "r"(b[1]));
}

// smem strides (floats), conflict-free fragment loads:
// A: addr = m*36 + k  -> bank (4*gid + tig), 32 distinct
// B: addr = k*264 + n -> bank (8*tig + gid), 32 distinct
#define SA2   36
#define SBN   264
#define A_FL  (128 * SA2)          // 4608 floats / stage
#define B_FL  (32 * SBN)           // 8448 floats / stage
#define ST_FL (A_FL + B_FL)        // 13056 floats / stage
#define SMEM_G_BYTES (3 * ST_FL * 4)   // 156672 B

// layer-1 single-shot layout: A 128x48 (stride 52), B 48x256 (stride 264)
#define SA1   52
#define A1_FL (128 * SA1)
#define B1_FL (48 * SBN)
#define SMEM_1_BYTES ((A1_FL + B1_FL) * 4)   // 77312 B

// ---------------- preprocessing ----------------
__global__ void init_kernel() {
    int i = blockIdx.x * blockDim.x + threadIdx.x;
    if (i < MP_MAX) g_perm[i] = -1;
    if (i < NAA) { g_counts[i] = 0; g_fill[i] = 0; }
}

__global__ void frame_kernel(const int* __restrict__ aa,
                             const float* __restrict__ pos14,
                             const int* __restrict__ mask) {
    int m = blockIdx.x * blockDim.x + threadIdx.x;
    if (m >= M_TOT) return;
    int a = aa[m];
    atomicAdd(&g_counts[a], 1);

    const float* p = pos14 + (size_t)m * 42;
    float cx = p[3], cy = p[4], cz = p[5];
    float v1x = p[6] - cx, v1y = p[7] - cy, v1z = p[8] - cz;
    float n1 = sqrtf(v1x*v1x + v1y*v1y + v1z*v1z) + EPSF;
    float e1x = v1x / n1, e1y = v1y / n1, e1z = v1z / n1;
    float v2x = p[0] - cx, v2y = p[1] - cy, v2z = p[2] - cz;
    float d  = e1x*v2x + e1y*v2y + e1z*v2z;
    float u2x = v2x - d*e1x, u2y = v2y - d*e1y, u2z = v2z - d*e1z;
    float n2 = sqrtf(u2x*u2x + u2y*u2y + u2z*u2z) + EPSF;
    float e2x = u2x / n2, e2y = u2y / n2, e2z = u2z / n2;
    float e3x = e1y*e2z - e1z*e2y;
    float e3y = e1z*e2x - e1x*e2z;
    float e3z = e1x*e2y - e1y*e2x;

    float* out = g_crd + (size_t)m * 48;
#pragma unroll
    for (int at = 0; at < 14; at++) {
        float qx = p[at*3+0] - cx, qy = p[at*3+1] - cy, qz = p[at*3+2] - cz;
        bool mk = mask[m*14 + at] != 0;
        out[at*3+0] = mk ? to_tf32(e1x*qx + e1y*qy + e1z*qz) : 0.f;
        out[at*3+1] = mk ? to_tf32(e2x*qx + e2y*qy + e2z*qz) : 0.f;
        out[at*3+2] = mk ? to_tf32(e3x*qx + e3y*qy + e3z*qz) : 0.f;
    }
#pragma unroll
    for (int k = 42; k < 48; k++) out[k] = 0.f;
}

__global__ void plan_kernel() {
    int off = 0, t = 0;
    for (int a = 0; a < NAA; a++) {
        g_offs[a] = off;
        int nt = (g_counts[a] + 127) >> 7;
        for (int i = 0; i < nt; i++) g_tile_aa[t++] = a;
        off += nt << 7;
    }
    for (; t < NT_ROW; t++) g_tile_aa[t] = -1;
}

__global__ void scatter_kernel(const int* __restrict__ aa) {
    int m = blockIdx.x * blockDim.x + threadIdx.x;
    if (m >= M_TOT) return;
    int a = aa[m];
    int pos = atomicAdd(&g_fill[a], 1);
    g_perm[g_offs[a] + pos] = m;
}

__global__ void bias1_kernel(const float* __restrict__ embed,
                             const float* __restrict__ w1,
                             const float* __restrict__ b1) {
    int a = blockIdx.y;
    int j = blockIdx.x * 128 + threadIdx.x;
    float acc = b1[j];
    for (int k = 0; k < FEAT; k++)
        acc += embed[a * FEAT + k] * w1[(size_t)(882 + k) * F2 + j];
    g_bias1[a * F2 + j] = acc;
}

__global__ void w1p_kernel(const float* __restrict__ w1) {
    int i = blockIdx.x * blockDim.x + threadIdx.x;
    if (i >= NAA * 48 * F2) return;
    int n = i & (F2 - 1);
    int r = i >> 10;
    int k = r % 48, cls = r / 48;
    g_w1p[i] = (k < 42) ? to_tf32(w1[(size_t)(cls * 42 + k) * F2 + n]) : 0.f;
}

__global__ void round_kernel(const float* __restrict__ src, float* __restrict__ dst, int n) {
    int i = blockIdx.x * blockDim.x + threadIdx.x;
    if (i < n) dst[i] = to_tf32(src[i]);
}

// ---------------- GEMM layers 2-4: CTA 128x256, 8 warps (2m x 4n) of 64x64 ----------------
template<int K, bool RELU, bool SCATTER>
__global__ __launch_bounds__(256, 1) void gemm_mma(const float* __restrict__ A,
                                                   const float* __restrict__ W,
                                                   const float* __restrict__ bias,
                                                   float* __restrict__ C) {
    int by = blockIdx.y;
    if (g_tile_aa[by] < 0) return;
    extern __shared__ float sm[];

    int tid = threadIdx.x;
    int bx = blockIdx.x;
    int rowbase = by * 128;
    int c_base = bx * 256;

    int wid = tid >> 5, lane = tid & 31;
    int wm = wid & 1, wn = wid >> 1;
    int gid = lane >> 2, tig = lane & 3;

    const float* Ab = A + (size_t)rowbase * K;
    const int NS = K / 32;

    // cp.async addressing
    int arow = tid >> 1, asg = tid & 1;                // 2 chunk-sets for A? no: A 1024 chunks
    // A: 128 rows x 32 k = 1024 chunks (16B); thread handles 4: f = tid + i*256
    // B: 32 rows x 256 n = 2048 chunks; thread handles 8
    (void)arow; (void)asg;

    float acc[4][8][4];
#pragma unroll
    for (int i = 0; i < 4; i++)
#pragma unroll
        for (int j = 0; j < 8; j++)
#pragma unroll
            for (int q = 0; q < 4; q++) acc[i][j][q] = 0.f;

    auto load_stage = [&](int s) {
        int buf = s % 3;
        float* As = sm + buf * ST_FL;
        float* Bs = As + A_FL;
#pragma unroll
        for (int i = 0; i < 4; i++) {
            int f = tid + i * 256;
            int row = f >> 3, sg = f & 7;
            cp16(smem_u32(&As[row * SA2 + sg * 4]),
                 Ab + (size_t)row * K + s * 32 + sg * 4);
        }
#pragma unroll
        for (int i = 0; i < 8; i++) {
            int f = tid + i * 256;
            int kr = f >> 6, sg = f & 63;
            cp16(smem_u32(&Bs[kr * SBN + sg * 4]),
                 W + (size_t)(s * 32 + kr) * 512 + c_base + sg * 4);
        }
    };

    load_stage(0); CP_COMMIT();
    load_stage(1); CP_COMMIT();

    for (int s = 0; s < NS; s++) {
        CP_WAIT(1);
        __syncthreads();
        if (s + 2 < NS) load_stage(s + 2);
        CP_COMMIT();

        int buf = s % 3;
        const float* As = sm + buf * ST_FL;
        const float* Bs = As + A_FL;
#pragma unroll
        for (int kt = 0; kt < 4; kt++) {
            int kb = kt * 8;
            uint32_t af[4][4], bf[8][2];
#pragma unroll
            for (int mt = 0; mt < 4; mt++) {
                int am = wm * 64 + mt * 16 + gid;
                const float* ap = As + am * SA2 + kb + tig;
                af[mt][0] = __float_as_uint(ap[0]);
                af[mt][1] = __float_as_uint(ap[8 * SA2]);
                af[mt][2] = __float_as_uint(ap[4]);
                af[mt][3] = __float_as_uint(ap[8 * SA2 + 4]);
            }
#pragma unroll
            for (int nt = 0; nt < 8; nt++) {
                int bn = wn * 64 + nt * 8 + gid;
                const float* bp = Bs + (kb + tig) * SBN + bn;
                bf[nt][0] = __float_as_uint(bp[0]);
                bf[nt][1] = __float_as_uint(bp[4 * SBN]);
            }
#pragma unroll
            for (int mt = 0; mt < 4; mt++)
#pragma unroll
                for (int nt = 0; nt < 8; nt++)
                    mma8(acc[mt][nt], af[mt], bf[nt]);
        }
        __syncthreads();
    }

    // epilogue
#pragma unroll
    for (int mt = 0; mt < 4; mt++) {
        int r0 = rowbase + wm * 64 + mt * 16 + gid;
        int r1 = r0 + 8;
        float *d0 = nullptr, *d1 = nullptr;
        if (SCATTER) {
            int m0 = g_perm[r0], m1 = g_perm[r1];
            if (m0 >= 0) d0 = C + (size_t)m0 * FEAT;
            if (m1 >= 0) d1 = C + (size_t)m1 * FEAT;
        } else {
            d0 = C + (size_t)r0 * FEAT;
            d1 = C + (size_t)r1 * FEAT;
        }
#pragma unroll
        for (int nt = 0; nt < 8; nt++) {
            int c = c_base + wn * 64 + nt * 8 + tig * 2;
            float bx0 = bias[c], bx1 = bias[c + 1];
            float2 v0, v1;
            v0.x = acc[mt][nt][0] + bx0; v0.y = acc[mt][nt][1] + bx1;
            v1.x = acc[mt][nt][2] + bx0; v1.y = acc[mt][nt][3] + bx1;
            if (RELU) {
                v0.x = to_tf32(fmaxf(v0.x, 0.f)); v0.y = to_tf32(fmaxf(v0.y, 0.f));
                v1.x = to_tf32(fmaxf(v1.x, 0.f)); v1.y = to_tf32(fmaxf(v1.y, 0.f));
            }
            if (d0) *(float2*)(d0 + c) = v0;
            if (d1) *(float2*)(d1 + c) = v1;
        }
    }
}

// ---------------- GEMM layer 1: gathered A (K=48), per-class W, CTA 128x256 ----------------
__global__ __launch_bounds__(256, 1) void gemm1_mma() {
    int by = blockIdx.y;
    int cls = g_tile_aa[by];
    if (cls < 0) return;
    extern __shared__ float sm[];
    float* As = sm;                 // 128 x 48, stride 52
    float* Bs = sm + A1_FL;         // 48 x 256, stride 264

    int tid = threadIdx.x;
    int bx = blockIdx.x;            // 0..3 over N=1024
    int rowbase = by * 128;
    int c_base = bx * 256;

    int wid = tid >> 5, lane = tid & 31;
    int wm = wid & 1, wn = wid >> 1;
    int gid = lane >> 2, tig = lane & 3;

    // A: 1536 chunks (12 per row), 6 per thread
#pragma unroll
    for (int i = 0; i < 6; i++) {
        int f = tid + i * 256;
        int row = f / 12, j = f % 12;
        int m = g_perm[rowbase + row]; if (m < 0) m = 0;
        cp16(smem_u32(&As[row * SA1 + j * 4]), g_crd + (size_t)m * 48 + j * 4);
    }
    // B: 48 x 256 = 3072 chunks, 12 per thread
    const float* Wb = g_w1p + (size_t)cls * 48 * F2;
#pragma unroll
    for (int i = 0; i < 12; i++) {
        int f = tid + i * 256;
        int kr = f >> 6, sg = f & 63;
        cp16(smem_u32(&Bs[kr * SBN + sg * 4]), Wb + (size_t)kr * F2 + c_base + sg * 4);
    }
    CP_COMMIT();
    CP_WAIT(0);
    __syncthreads();

    float acc[4][8][4];
#pragma unroll
    for (int i = 0; i < 4; i++)
#pragma unroll
        for (int j = 0; j < 8; j++)
#pragma unroll
            for (int q = 0; q < 4; q++) acc[i][j][q] = 0.f;

#pragma unroll
    for (int kt = 0; kt < 6; kt++) {
        int kb = kt * 8;
        uint32_t af[4][4], bf[8][2];
#pragma unroll
        for (int mt = 0; mt < 4; mt++) {
            int am = wm * 64 + mt * 16 + gid;
            const float* ap = As + am * SA1 + kb + tig;
            af[mt][0] = __float_as_uint(ap[0]);
            af[mt][1] = __float_as_uint(ap[8 * SA1]);
            af[mt][2] = __float_as_uint(ap[4]);
            af[mt][3] = __float_as_uint(ap[8 * SA1 + 4]);
        }
#pragma unroll
        for (int nt = 0; nt < 8; nt++) {
            int bn = wn * 64 + nt * 8 + gid;
            const float* bp = Bs + (kb + tig) * SBN + bn;
            bf[nt][0] = __float_as_uint(bp[0]);
            bf[nt][1] = __float_as_uint(bp[4 * SBN]);
        }
#pragma unroll
        for (int mt = 0; mt < 4; mt++)
#pragma unroll
            for (int nt = 0; nt < 8; nt++)
                mma8(acc[mt][nt], af[mt], bf[nt]);
    }

    const float* bp = g_bias1 + cls * F2;
#pragma unroll
    for (int mt = 0; mt < 4; mt++) {
        int r0 = rowbase + wm * 64 + mt * 16 + gid;
        float* d0 = g_h1 + (size_t)r0 * F2;
        float* d1 = d0 + (size_t)8 * F2;
#pragma unroll
        for (int nt = 0; nt < 8; nt++) {
            int c = c_base + wn * 64 + nt * 8 + tig * 2;
            float bx0 = bp[c], bx1 = bp[c + 1];
            float2 v0, v1;
            v0.x = to_tf32(fmaxf(acc[mt][nt][0] + bx0, 0.f));
            v0.y = to_tf32(fmaxf(acc[mt][nt][1] + bx1, 0.f));
            v1.x = to_tf32(fmaxf(acc[mt][nt][2] + bx0, 0.f));
            v1.y = to_tf32(fmaxf(acc[mt][nt][3] + bx1, 0.f));
            *(float2*)(d0 + c) = v0;
            *(float2*)(d1 + c) = v1;
        }
    }
}

// ---------------- launch ----------------
extern "C" void kernel_launch(void* const* d_in, const int* in_sizes, int n_in,
                              void* d_out, int out_size) {
    const int*   aa    = (const int*)  d_in[0];
    const float* pos14 = (const float*)d_in[1];
    const int*   mask  = (const int*)  d_in[2];
    const float* embed = (const float*)d_in[3];
    const float* w1    = (const float*)d_in[4];
    const float* b1    = (const float*)d_in[5];
    const float* w2    = (const float*)d_in[6];
    const float* b2    = (const float*)d_in[7];
    const float* w3    = (const float*)d_in[8];
    const float* b3    = (const float*)d_in[9];
    const float* w4    = (const float*)d_in[10];
    const float* b4    = (const float*)d_in[11];
    float* out = (float*)d_out;

    void *p_h1, *p_h2, *p_h3, *p_w2r, *p_w3r, *p_w4r;
    cudaGetSymbolAddress(&p_h1, g_h1);
    cudaGetSymbolAddress(&p_h2, g_h2);
    cudaGetSymbolAddress(&p_h3, g_h3);
    cudaGetSymbolAddress(&p_w2r, g_w2r);
    cudaGetSymbolAddress(&p_w3r, g_w3r);
    cudaGetSymbolAddress(&p_w4r, g_w4r);

    cudaFuncSetAttribute(gemm1_mma, cudaFuncAttributeMaxDynamicSharedMemorySize, SMEM_1_BYTES);
    cudaFuncSetAttribute(gemm_mma<1024, true,  false>, cudaFuncAttributeMaxDynamicSharedMemorySize, SMEM_G_BYTES);
    cudaFuncSetAttribute(gemm_mma<512,  true,  false>, cudaFuncAttributeMaxDynamicSharedMemorySize, SMEM_G_BYTES);
    cudaFuncSetAttribute(gemm_mma<512,  false, true >, cudaFuncAttributeMaxDynamicSharedMemorySize, SMEM_G_BYTES);

    init_kernel<<<(MP_MAX + 255) / 256, 256>>>();
    frame_kernel<<<M_TOT / 256, 256>>>(aa, pos14, mask);
    plan_kernel<<<1, 1>>>();
    scatter_kernel<<<M_TOT / 256, 256>>>(aa);
    bias1_kernel<<<dim3(F2 / 128, NAA), 128>>>(embed, w1, b1);
    w1p_kernel<<<(NAA * 48 * F2 + 255) / 256, 256>>>(w1);
    round_kernel<<<(F2 * FEAT + 255) / 256, 256>>>(w2, (float*)p_w2r, F2 * FEAT);
    round_kernel<<<(FEAT * FEAT + 255) / 256, 256>>>(w3, (float*)p_w3r, FEAT * FEAT);
    round_kernel<<<(FEAT * FEAT + 255) / 256, 256>>>(w4, (float*)p_w4r, FEAT * FEAT);

    gemm1_mma<<<dim3(4, NT_ROW), 256, SMEM_1_BYTES>>>();
    gemm_mma<1024, true,  false><<<dim3(2, NT_ROW), 256, SMEM_G_BYTES>>>((const float*)p_h1, (const float*)p_w2r, b2, (float*)p_h2);
    gemm_mma<512,  true,  false><<<dim3(2, NT_ROW), 256, SMEM_G_BYTES>>>((const float*)p_h2, (const float*)p_w3r, b3, (float*)p_h3);
    gemm_mma<512,  false, true ><<<dim3(2, NT_ROW), 256, SMEM_G_BYTES>>>((const float*)p_h3, (const float*)p_w4r, b4, out);
    (void)in_sizes; (void)n_in; (void)out_size;
}

// round 9
// speedup vs baseline: 4.3991x; 1.4781x over previous
#include <cuda_runtime.h>
#include <cuda_fp16.h>
#include <cstdint>
#include <math.h>

// ---------------- problem constants ----------------
#define M_TOT   65536
#define FEAT    512
#define F2      1024
#define NAA     21
#define EPSF    1e-6f
#define NT_ROW  533
#define MP_MAX  (NT_ROW * 128)

// ---------------- device scratch ----------------
__device__ __align__(16) __half  g_crdh[(size_t)M_TOT * 48];
__device__ __align__(16) __half  g_h1[(size_t)MP_MAX * F2];
__device__ __align__(16) __half  g_h2[(size_t)MP_MAX * FEAT];
__device__ __align__(16) __half  g_h3[(size_t)MP_MAX * FEAT];
__device__ __align__(16) __half2 g_w1h[(size_t)NAA * 24 * F2];   // [cls][k2<24][n]
__device__ __align__(16) __half2 g_w2h[(size_t)512 * FEAT];      // [k2][n]
__device__ __align__(16) __half2 g_w3h[(size_t)256 * FEAT];
__device__ __align__(16) __half2 g_w4h[(size_t)256 * FEAT];
__device__ __align__(16) float g_bias1[NAA * F2];
__device__ int g_counts[NAA];
__device__ int g_fill[NAA];
__device__ int g_offs[NAA];
__device__ int g_perm[MP_MAX];
__device__ int g_tile_aa[NT_ROW];

// ---------------- helpers ----------------
__device__ __forceinline__ uint32_t smem_u32(const void* p) {
    uint32_t a;
    asm("{ .reg .u64 t; cvta.to.shared.u64 t, %1; cvt.u32.u64 %0, t; }" : "=r"(a) : "l"(p));
    return a;
}
__device__ __forceinline__ void cp16(uint32_t dst, const void* src) {
    asm volatile("cp.async.cg.shared.global [%0], [%1], 16;" :: "r"(dst), "l"(src));
}
#define CP_COMMIT() asm volatile("cp.async.commit_group;" ::: "memory")
#define CP_WAIT(n)  asm volatile("cp.async.wait_group %0;" :: "n"(n) : "memory")

__device__ __forceinline__ void mma16(float* c, const uint32_t* a, const uint32_t* b) {
    asm volatile(
        "mma.sync.aligned.m16n8k16.row.col.f32.f16.f16.f32 "
        "{%0,%1,%2,%3}, {%4,%5,%6,%7}, {%8,%9}, {%0,%1,%2,%3};"
        : "+f"(c[0]), "+f"(c[1]), "+f"(c[2]), "+f"(c[3])
        : "r"(a[0]), "r"(a[1]), "r"(a[2]), "r"(a[3]), "r"(b[0]), "r"(b[1]));
}
__device__ __forceinline__ void ldmA(uint32_t* r, uint32_t addr) {
    asm volatile("ldmatrix.sync.aligned.m8n8.x4.shared.b16 {%0,%1,%2,%3}, [%4];"
        : "=r"(r[0]), "=r"(r[1]), "=r"(r[2]), "=r"(r[3]) : "r"(addr));
}

// smem strides (in half2 words)
#define SA2   20     // layers 2-4: A row = 16 data + 4 pad  (80 B/row)
#define SA1   28     // layer  1 : A row = 24 data + 4 pad  (112 B/row)
#define SBN   264    // B row = 256 data + 8 pad
#define A_H2  (128 * SA2)
#define B_H2  (16 * SBN)
#define ST_H2 (A_H2 + B_H2)
#define SMEM_G_BYTES (3 * ST_H2 * 4)                 // 81408 B
#define SMEM_1_BYTES ((128 * SA1 + 24 * SBN) * 4)    // 39680 B

// ---------------- preprocessing ----------------
__global__ void init_kernel() {
    int i = blockIdx.x * blockDim.x + threadIdx.x;
    if (i < MP_MAX) g_perm[i] = -1;
    if (i < NAA) { g_counts[i] = 0; g_fill[i] = 0; }
}

__global__ void frame_kernel(const int* __restrict__ aa,
                             const float* __restrict__ pos14,
                             const int* __restrict__ mask) {
    int m = blockIdx.x * blockDim.x + threadIdx.x;
    if (m >= M_TOT) return;
    int a = aa[m];
    atomicAdd(&g_counts[a], 1);

    const float* p = pos14 + (size_t)m * 42;
    float cx = p[3], cy = p[4], cz = p[5];
    float v1x = p[6] - cx, v1y = p[7] - cy, v1z = p[8] - cz;
    float n1 = sqrtf(v1x*v1x + v1y*v1y + v1z*v1z) + EPSF;
    float e1x = v1x / n1, e1y = v1y / n1, e1z = v1z / n1;
    float v2x = p[0] - cx, v2y = p[1] - cy, v2z = p[2] - cz;
    float d  = e1x*v2x + e1y*v2y + e1z*v2z;
    float u2x = v2x - d*e1x, u2y = v2y - d*e1y, u2z = v2z - d*e1z;
    float n2 = sqrtf(u2x*u2x + u2y*u2y + u2z*u2z) + EPSF;
    float e2x = u2x / n2, e2y = u2y / n2, e2z = u2z / n2;
    float e3x = e1y*e2z - e1z*e2y;
    float e3y = e1z*e2x - e1x*e2z;
    float e3z = e1x*e2y - e1y*e2x;

    __half* out = g_crdh + (size_t)m * 48;
#pragma unroll
    for (int at = 0; at < 14; at++) {
        float qx = p[at*3+0] - cx, qy = p[at*3+1] - cy, qz = p[at*3+2] - cz;
        bool mk = mask[m*14 + at] != 0;
        out[at*3+0] = __float2half_rn(mk ? (e1x*qx + e1y*qy + e1z*qz) : 0.f);
        out[at*3+1] = __float2half_rn(mk ? (e2x*qx + e2y*qy + e2z*qz) : 0.f);
        out[at*3+2] = __float2half_rn(mk ? (e3x*qx + e3y*qy + e3z*qz) : 0.f);
    }
#pragma unroll
    for (int k = 42; k < 48; k++) out[k] = __float2half_rn(0.f);
}

__global__ void plan_kernel() {
    int off = 0, t = 0;
    for (int a = 0; a < NAA; a++) {
        g_offs[a] = off;
        int nt = (g_counts[a] + 127) >> 7;
        for (int i = 0; i < nt; i++) g_tile_aa[t++] = a;
        off += nt << 7;
    }
    for (; t < NT_ROW; t++) g_tile_aa[t] = -1;
}

__global__ void scatter_kernel(const int* __restrict__ aa) {
    int m = blockIdx.x * blockDim.x + threadIdx.x;
    if (m >= M_TOT) return;
    int a = aa[m];
    int pos = atomicAdd(&g_fill[a], 1);
    g_perm[g_offs[a] + pos] = m;
}

__global__ void bias1_kernel(const float* __restrict__ embed,
                             const float* __restrict__ w1,
                             const float* __restrict__ b1) {
    int a = blockIdx.y;
    int j = blockIdx.x * 128 + threadIdx.x;
    float acc = b1[j];
    for (int k = 0; k < FEAT; k++)
        acc += embed[a * FEAT + k] * w1[(size_t)(882 + k) * F2 + j];
    g_bias1[a * F2 + j] = acc;
}

// g_w1h[cls][k2][n] = half2(w1[cls*42+2k2][n], w1[cls*42+2k2+1][n]), zero pad k>=42
__global__ void w1h_kernel(const float* __restrict__ w1) {
    int i = blockIdx.x * blockDim.x + threadIdx.x;
    if (i >= NAA * 24 * F2) return;
    int n = i & (F2 - 1);
    int r = i >> 10;
    int k2 = r % 24, cls = r / 24;
    float v0 = (2 * k2     < 42) ? w1[(size_t)(cls * 42 + 2 * k2    ) * F2 + n] : 0.f;
    float v1 = (2 * k2 + 1 < 42) ? w1[(size_t)(cls * 42 + 2 * k2 + 1) * F2 + n] : 0.f;
    g_w1h[i] = __floats2half2_rn(v0, v1);
}

// dst[k2][n] = half2(src[2k2][n], src[2k2+1][n]);  src is [K][512]
__global__ void packw_kernel(const float* __restrict__ src, __half2* __restrict__ dst, int k2max) {
    int i = blockIdx.x * blockDim.x + threadIdx.x;
    if (i >= k2max * FEAT) return;
    int n = i & (FEAT - 1), k2 = i >> 9;
    dst[i] = __floats2half2_rn(src[(size_t)(2 * k2) * FEAT + n],
                               src[(size_t)(2 * k2 + 1) * FEAT + n]);
}

// ---------------- GEMM layers 2-4: CTA 128x256, 8 warps (2m x 4n) of 64x64, fp16 ----------------
// K in halves. RELU=true -> half output (dense); RELU=false -> float output (scatter).
template<int K, bool RELU>
__global__ __launch_bounds__(256, 1) void gemm_mma(const __half* __restrict__ A,
                                                   const __half2* __restrict__ W,
                                                   const float* __restrict__ bias,
                                                   void* __restrict__ Cv) {
    int by = blockIdx.y;
    if (g_tile_aa[by] < 0) return;
    extern __shared__ __align__(16) char smc[];
    __half2* sm = (__half2*)smc;

    int tid = threadIdx.x;
    int bx = blockIdx.x;
    int rowbase = by * 128;
    int c_base = bx * 256;

    int wid = tid >> 5, lane = tid & 31;
    int wm = wid & 1, wn = wid >> 1;
    int gid = lane >> 2, tig = lane & 3;

    const __half* Ab = A + (size_t)rowbase * K;
    const int NS = K / 32;

    float acc[4][8][4];
#pragma unroll
    for (int i = 0; i < 4; i++)
#pragma unroll
        for (int j = 0; j < 8; j++)
#pragma unroll
            for (int q = 0; q < 4; q++) acc[i][j][q] = 0.f;

    auto load_stage = [&](int s) {
        int buf = s % 3;
        __half2* As = sm + buf * ST_H2;
        __half2* Bs = As + A_H2;
#pragma unroll
        for (int i = 0; i < 2; i++) {
            int f = tid + i * 256;
            int row = f >> 2, sg = f & 3;
            cp16(smem_u32(&As[row * SA2 + sg * 4]),
                 Ab + (size_t)row * K + s * 32 + sg * 8);
        }
#pragma unroll
        for (int i = 0; i < 4; i++) {
            int f = tid + i * 256;
            int kr = f >> 6, sg = f & 63;
            cp16(smem_u32(&Bs[kr * SBN + sg * 4]),
                 W + (size_t)(s * 16 + kr) * FEAT + c_base + sg * 4);
        }
    };

    load_stage(0); CP_COMMIT();
    load_stage(1); CP_COMMIT();

    int lrow = lane & 15, lkg = lane >> 4;
    for (int s = 0; s < NS; s++) {
        CP_WAIT(1);
        __syncthreads();
        if (s + 2 < NS) load_stage(s + 2);
        CP_COMMIT();

        int buf = s % 3;
        __half2* As = sm + buf * ST_H2;
        const uint32_t* Bs32 = (const uint32_t*)(As + A_H2);
        uint32_t As_addr = smem_u32(As);
#pragma unroll
        for (int kt = 0; kt < 2; kt++) {
            uint32_t af[4][4], bf[8][2];
#pragma unroll
            for (int mt = 0; mt < 4; mt++) {
                int am = wm * 64 + mt * 16 + lrow;
                ldmA(af[mt], As_addr + am * (SA2 * 4) + kt * 32 + lkg * 16);
            }
#pragma unroll
            for (int nt = 0; nt < 8; nt++) {
                int bn = wn * 64 + nt * 8 + gid;
                int k2 = kt * 8 + tig;
                bf[nt][0] = Bs32[k2 * SBN + bn];
                bf[nt][1] = Bs32[(k2 + 4) * SBN + bn];
            }
#pragma unroll
            for (int mt = 0; mt < 4; mt++)
#pragma unroll
                for (int nt = 0; nt < 8; nt++)
                    mma16(acc[mt][nt], af[mt], bf[nt]);
        }
        __syncthreads();
    }

    // epilogue
#pragma unroll
    for (int mt = 0; mt < 4; mt++) {
        int r0 = rowbase + wm * 64 + mt * 16 + gid;
        int r1 = r0 + 8;
        if (RELU) {
            __half* C = (__half*)Cv;
            __half* d0 = C + (size_t)r0 * FEAT;
            __half* d1 = C + (size_t)r1 * FEAT;
#pragma unroll
            for (int nt = 0; nt < 8; nt++) {
                int c = c_base + wn * 64 + nt * 8 + tig * 2;
                float bx0 = bias[c], bx1 = bias[c + 1];
                *(__half2*)(d0 + c) = __floats2half2_rn(fmaxf(acc[mt][nt][0] + bx0, 0.f),
                                                        fmaxf(acc[mt][nt][1] + bx1, 0.f));
                *(__half2*)(d1 + c) = __floats2half2_rn(fmaxf(acc[mt][nt][2] + bx0, 0.f),
                                                        fmaxf(acc[mt][nt][3] + bx1, 0.f));
            }
        } else {
            float* C = (float*)Cv;
            int m0 = g_perm[r0], m1 = g_perm[r1];
            float* d0 = (m0 >= 0) ? C + (size_t)m0 * FEAT : nullptr;
            float* d1 = (m1 >= 0) ? C + (size_t)m1 * FEAT : nullptr;
#pragma unroll
            for (int nt = 0; nt < 8; nt++) {
                int c = c_base + wn * 64 + nt * 8 + tig * 2;
                float bx0 = bias[c], bx1 = bias[c + 1];
                if (d0) { float2 v; v.x = acc[mt][nt][0] + bx0; v.y = acc[mt][nt][1] + bx1;
                          *(float2*)(d0 + c) = v; }
                if (d1) { float2 v; v.x = acc[mt][nt][2] + bx0; v.y = acc[mt][nt][3] + bx1;
                          *(float2*)(d1 + c) = v; }
            }
        }
    }
}

// ---------------- GEMM layer 1: gathered A (K=48), per-class W, CTA 128x256, fp16 ----------------
__global__ __launch_bounds__(256, 1) void gemm1_mma() {
    int by = blockIdx.y;
    int cls = g_tile_aa[by];
    if (cls < 0) return;
    extern __shared__ __align__(16) char smc[];
    __half2* As = (__half2*)smc;            // 128 x SA1
    __half2* Bs = As + 128 * SA1;           // 24 x SBN

    int tid = threadIdx.x;
    int bx = blockIdx.x;                    // 0..3 over N=1024
    int rowbase = by * 128;
    int c_base = bx * 256;

    int wid = tid >> 5, lane = tid & 31;
    int wm = wid & 1, wn = wid >> 1;
    int gid = lane >> 2, tig = lane & 3;

    // A: 128 rows x 48 halves = 768 16B-chunks, 3 per thread
#pragma unroll
    for (int i = 0; i < 3; i++) {
        int f = tid + i * 256;
        int row = f / 6, j = f % 6;
        int m = g_perm[rowbase + row]; if (m < 0) m = 0;
        cp16(smem_u32(&As[row * SA1 + j * 4]), g_crdh + (size_t)m * 48 + j * 8);
    }
    // B: 24 k2-rows x 256 half2 = 1536 chunks, 6 per thread
    const __half2* Wb = g_w1h + (size_t)cls * 24 * F2;
#pragma unroll
    for (int i = 0; i < 6; i++) {
        int f = tid + i * 256;
        int kr = f >> 6, sg = f & 63;
        cp16(smem_u32(&Bs[kr * SBN + sg * 4]), Wb + (size_t)kr * F2 + c_base + sg * 4);
    }
    CP_COMMIT();
    CP_WAIT(0);
    __syncthreads();

    float acc[4][8][4];
#pragma unroll
    for (int i = 0; i < 4; i++)
#pragma unroll
        for (int j = 0; j < 8; j++)
#pragma unroll
            for (int q = 0; q < 4; q++) acc[i][j][q] = 0.f;

    const uint32_t* Bs32 = (const uint32_t*)Bs;
    uint32_t As_addr = smem_u32(As);
    int lrow = lane & 15, lkg = lane >> 4;
#pragma unroll
    for (int kt = 0; kt < 3; kt++) {
        uint32_t af[4][4], bf[8][2];
#pragma unroll
        for (int mt = 0; mt < 4; mt++) {
            int am = wm * 64 + mt * 16 + lrow;
            ldmA(af[mt], As_addr + am * (SA1 * 4) + kt * 32 + lkg * 16);
        }
#pragma unroll
        for (int nt = 0; nt < 8; nt++) {
            int bn = wn * 64 + nt * 8 + gid;
            int k2 = kt * 8 + tig;
            bf[nt][0] = Bs32[k2 * SBN + bn];
            bf[nt][1] = Bs32[(k2 + 4) * SBN + bn];
        }
#pragma unroll
        for (int mt = 0; mt < 4; mt++)
#pragma unroll
            for (int nt = 0; nt < 8; nt++)
                mma16(acc[mt][nt], af[mt], bf[nt]);
    }

    const float* bp = g_bias1 + cls * F2;
#pragma unroll
    for (int mt = 0; mt < 4; mt++) {
        int r0 = rowbase + wm * 64 + mt * 16 + gid;
        __half* d0 = g_h1 + (size_t)r0 * F2;
        __half* d1 = d0 + (size_t)8 * F2;
#pragma unroll
        for (int nt = 0; nt < 8; nt++) {
            int c = c_base + wn * 64 + nt * 8 + tig * 2;
            float bx0 = bp[c], bx1 = bp[c + 1];
            *(__half2*)(d0 + c) = __floats2half2_rn(fmaxf(acc[mt][nt][0] + bx0, 0.f),
                                                    fmaxf(acc[mt][nt][1] + bx1, 0.f));
            *(__half2*)(d1 + c) = __floats2half2_rn(fmaxf(acc[mt][nt][2] + bx0, 0.f),
                                                    fmaxf(acc[mt][nt][3] + bx1, 0.f));
        }
    }
}

// ---------------- launch ----------------
extern "C" void kernel_launch(void* const* d_in, const int* in_sizes, int n_in,
                              void* d_out, int out_size) {
    const int*   aa    = (const int*)  d_in[0];
    const float* pos14 = (const float*)d_in[1];
    const int*   mask  = (const int*)  d_in[2];
    const float* embed = (const float*)d_in[3];
    const float* w1    = (const float*)d_in[4];
    const float* b1    = (const float*)d_in[5];
    const float* w2    = (const float*)d_in[6];
    const float* b2    = (const float*)d_in[7];
    const float* w3    = (const float*)d_in[8];
    const float* b3    = (const float*)d_in[9];
    const float* w4    = (const float*)d_in[10];
    const float* b4    = (const float*)d_in[11];
    float* out = (float*)d_out;

    void *p_h1, *p_h2, *p_h3, *p_w2h, *p_w3h, *p_w4h;
    cudaGetSymbolAddress(&p_h1, g_h1);
    cudaGetSymbolAddress(&p_h2, g_h2);
    cudaGetSymbolAddress(&p_h3, g_h3);
    cudaGetSymbolAddress(&p_w2h, g_w2h);
    cudaGetSymbolAddress(&p_w3h, g_w3h);
    cudaGetSymbolAddress(&p_w4h, g_w4h);

    cudaFuncSetAttribute(gemm1_mma, cudaFuncAttributeMaxDynamicSharedMemorySize, SMEM_1_BYTES);
    cudaFuncSetAttribute(gemm_mma<1024, true >, cudaFuncAttributeMaxDynamicSharedMemorySize, SMEM_G_BYTES);
    cudaFuncSetAttribute(gemm_mma<512,  true >, cudaFuncAttributeMaxDynamicSharedMemorySize, SMEM_G_BYTES);
    cudaFuncSetAttribute(gemm_mma<512,  false>, cudaFuncAttributeMaxDynamicSharedMemorySize, SMEM_G_BYTES);

    init_kernel<<<(MP_MAX + 255) / 256, 256>>>();
    frame_kernel<<<M_TOT / 256, 256>>>(aa, pos14, mask);
    plan_kernel<<<1, 1>>>();
    scatter_kernel<<<M_TOT / 256, 256>>>(aa);
    bias1_kernel<<<dim3(F2 / 128, NAA), 128>>>(embed, w1, b1);
    w1h_kernel<<<(NAA * 24 * F2 + 255) / 256, 256>>>(w1);
    packw_kernel<<<(512 * FEAT + 255) / 256, 256>>>(w2, (__half2*)p_w2h, 512);
    packw_kernel<<<(256 * FEAT + 255) / 256, 256>>>(w3, (__half2*)p_w3h, 256);
    packw_kernel<<<(256 * FEAT + 255) / 256, 256>>>(w4, (__half2*)p_w4h, 256);

    gemm1_mma<<<dim3(4, NT_ROW), 256, SMEM_1_BYTES>>>();
    gemm_mma<1024, true ><<<dim3(2, NT_ROW), 256, SMEM_G_BYTES>>>((const __half*)p_h1, (const __half2*)p_w2h, b2, p_h2);
    gemm_mma<512,  true ><<<dim3(2, NT_ROW), 256, SMEM_G_BYTES>>>((const __half*)p_h2, (const __half2*)p_w3h, b3, p_h3);
    gemm_mma<512,  false><<<dim3(2, NT_ROW), 256, SMEM_G_BYTES>>>((const __half*)p_h3, (const __half2*)p_w4h, b4, out);
    (void)in_sizes; (void)n_in; (void)out_size;
}